// round 1
// baseline (speedup 1.0000x reference)
#include <cuda_runtime.h>
#include <math.h>

#define HH 56
#define WW 56
#define NB 256
#define BATCH 8
#define CHANNELS 1024
#define PLANE (HH*WW)           // 3136
#define BC (BATCH*CHANNELS)     // 8192
#define NELEM (BC*PLANE)        // 25,690,112
#define T_THRESH 0.9f

// ------------------------- device scratch (no allocations) -------------------
__device__ unsigned int g_total[NB];
__device__ unsigned int g_col0[WW*NB];
__device__ unsigned int g_cell[HH*WW*NB];   // heavy path integral-hist scratch (12.8MB)
__device__ int   g_region[4];               // xs, xd, ys, yd
__device__ int   g_flag;                    // 1 => heavy path needed
__device__ float g_total_ent;
__device__ int   g_ys0;
__device__ float g_pooled[BC];

// ------------------------- helpers ------------------------------------------
__device__ __forceinline__ float blockReduceSum(float v) {
    __shared__ float s_red[32];
    unsigned lane = threadIdx.x & 31u;
    unsigned wid  = threadIdx.x >> 5;
    #pragma unroll
    for (int o = 16; o; o >>= 1) v += __shfl_xor_sync(0xffffffffu, v, o);
    if (lane == 0) s_red[wid] = v;
    __syncthreads();
    unsigned nw = (blockDim.x + 31u) >> 5;
    if (wid == 0) {
        float t = (lane < nw) ? s_red[lane] : 0.0f;
        #pragma unroll
        for (int o = 16; o; o >>= 1) t += __shfl_xor_sync(0xffffffffu, t, o);
        if (lane == 0) s_red[0] = t;
    }
    __syncthreads();
    float r = s_red[0];
    __syncthreads();
    return r;
}

__device__ __forceinline__ int bin_of(float v) {
    // matches clip(floor(v*256), 0, 255); caller guarantees v >= 0
    int b = (int)floorf(v * 256.0f);
    return b > 255 ? 255 : b;
}

// ------------------------- k0: zero small scratch ----------------------------
__global__ void k_zero_small() {
    for (int i = threadIdx.x; i < NB; i += blockDim.x) g_total[i] = 0u;
    for (int i = threadIdx.x; i < WW*NB; i += blockDim.x) g_col0[i] = 0u;
}

// ------------------------- k1a: full-image 256-bin histogram -----------------
__global__ void k_total_hist(const float4* __restrict__ x4, int n4) {
    __shared__ unsigned int sh[8 * NB];
    for (int i = threadIdx.x; i < 8 * NB; i += blockDim.x) sh[i] = 0u;
    __syncthreads();
    unsigned int* h = sh + ((threadIdx.x >> 5) & 7) * NB;
    int stride = gridDim.x * blockDim.x;
    for (int i = blockIdx.x * blockDim.x + threadIdx.x; i < n4; i += stride) {
        float4 v = x4[i];
        if (v.x >= 0.0f && v.x <= 1.0f) atomicAdd(&h[bin_of(v.x)], 1u);
        if (v.y >= 0.0f && v.y <= 1.0f) atomicAdd(&h[bin_of(v.y)], 1u);
        if (v.z >= 0.0f && v.z <= 1.0f) atomicAdd(&h[bin_of(v.z)], 1u);
        if (v.w >= 0.0f && v.w <= 1.0f) atomicAdd(&h[bin_of(v.w)], 1u);
    }
    __syncthreads();
    for (int i = threadIdx.x; i < NB; i += blockDim.x) {
        unsigned int s = 0;
        #pragma unroll
        for (int r = 0; r < 8; r++) s += sh[r * NB + i];
        if (s) atomicAdd(&g_total[i], s);
    }
}

// ------------------------- k1b: row-0 per-column histograms ------------------
// grid: 32 blocks = (whalf in {0,1}) x (16 bc-chunks of 512)
__global__ void k_col0_hist(const float* __restrict__ x) {
    __shared__ unsigned int sh[28 * NB];   // 28KB
    for (int i = threadIdx.x; i < 28 * NB; i += blockDim.x) sh[i] = 0u;
    __syncthreads();
    int whalf = blockIdx.x & 1;
    int chunk = blockIdx.x >> 1;
    int bc0 = chunk * 512;
    const int TOT = 512 * 28;
    for (int i = threadIdx.x; i < TOT; i += blockDim.x) {
        int bc   = bc0 + i / 28;
        int wloc = i % 28;
        float v = x[(size_t)bc * PLANE + whalf * 28 + wloc];  // h == 0
        if (v >= 0.0f && v <= 1.0f)
            atomicAdd(&sh[wloc * NB + bin_of(v)], 1u);
    }
    __syncthreads();
    for (int i = threadIdx.x; i < 28 * NB; i += blockDim.x) {
        unsigned int s = sh[i];
        if (s) atomicAdd(&g_col0[(whalf * 28 + (i >> 8)) * NB + (i & 255)], s);
    }
}

// ------------------------- k2: light EKLM (argmax + Ts0 decision) ------------
__global__ void k_eklm_light() {   // 1 block, 256 threads (tid == bin)
    int tid = threadIdx.x;
    float bestEnt = -1e30f;
    int bestw = 0;
    for (int w = 0; w < WW; w++) {
        float c = (float)g_col0[w * NB + tid];
        float s = blockReduceSum(c);
        float p = c / s;
        float ent = -blockReduceSum(p * log2f(p + 1e-9f));
        if (ent > bestEnt) { bestEnt = ent; bestw = w; }   // first-max tiebreak
    }
    // total entropy
    float c = (float)g_total[tid];
    float s = blockReduceSum(c);
    float p = c / s;
    float tot = -blockReduceSum(p * log2f(p + 1e-9f));

    if (tid == 0) {
        float Ts0 = bestEnt / tot;
        if (Ts0 < T_THRESH) {
            g_flag = 1;
            g_ys0 = bestw;
            g_total_ent = tot;
        } else {
            g_flag = 0;
            g_region[0] = 0; g_region[1] = 1;
            g_region[2] = bestw; g_region[3] = bestw + 1;
        }
    }
}

// ------------------------- heavy path (flag-gated; rarely runs) --------------
__global__ void k_zero_cell() {
    if (!g_flag) return;
    int stride = gridDim.x * blockDim.x;
    for (int i = blockIdx.x * blockDim.x + threadIdx.x; i < HH*WW*NB; i += stride)
        g_cell[i] = 0u;
}

// grid: 56 h x 2 whalf x 4 bc-chunks = 448 blocks
__global__ void k_cell_hist(const float* __restrict__ x) {
    if (!g_flag) return;
    __shared__ unsigned int sh[28 * NB];   // 28KB
    for (int i = threadIdx.x; i < 28 * NB; i += blockDim.x) sh[i] = 0u;
    __syncthreads();
    int h     = blockIdx.x % 56;
    int whalf = (blockIdx.x / 56) & 1;
    int chunk = blockIdx.x / 112;
    int bc0 = chunk * 2048;
    const int TOT = 2048 * 28;
    for (int i = threadIdx.x; i < TOT; i += blockDim.x) {
        int bc   = bc0 + i / 28;
        int wloc = i % 28;
        float v = x[(size_t)bc * PLANE + h * WW + whalf * 28 + wloc];
        if (v >= 0.0f && v <= 1.0f)
            atomicAdd(&sh[wloc * NB + bin_of(v)], 1u);
    }
    __syncthreads();
    for (int i = threadIdx.x; i < 28 * NB; i += blockDim.x) {
        unsigned int s = sh[i];
        if (s) atomicAdd(&g_cell[((size_t)(h * WW + whalf * 28 + (i >> 8))) * NB + (i & 255)], s);
    }
}

__global__ void k_cumsum_h() {   // 56 blocks (w), 256 threads (bin)
    if (!g_flag) return;
    int w = blockIdx.x, tid = threadIdx.x;
    unsigned int run = 0;
    for (int h = 0; h < HH; h++) {
        size_t idx = ((size_t)(h * WW + w)) * NB + tid;
        run += g_cell[idx];
        g_cell[idx] = run;
    }
}

__global__ void k_cumsum_w() {   // 56 blocks (h), 256 threads (bin)
    if (!g_flag) return;
    int h = blockIdx.x, tid = threadIdx.x;
    unsigned int run = 0;
    for (int w = 0; w < WW; w++) {
        size_t idx = ((size_t)(h * WW + w)) * NB + tid;
        run += g_cell[idx];
        g_cell[idx] = run;
    }
}

__device__ __forceinline__ float integA(int i, int j, int tid) {
    // padded integral hist lookup: A[i][j][tid], i,j in [0,56]
    if (i <= 0 || j <= 0) return 0.0f;
    return (float)g_cell[((size_t)((i - 1) * WW + (j - 1))) * NB + tid];
}

__device__ float region_ent(int xd, int ys, int yd, int tid) {
    float a = integA(xd, yd, tid) - integA(xd, ys, tid);
    float s = blockReduceSum(a);
    float p = a / s;
    return -blockReduceSum(p * log2f(p + 1e-9f));
}

__global__ void k_eklm_loop() {   // 1 block, 256 threads
    if (!g_flag) return;
    int tid = threadIdx.x;
    int xd = 1, ys = g_ys0, yd = g_ys0 + 1;
    float total = g_total_ent;
    float Ts = region_ent(xd, ys, yd, tid) / total;
    bool done = false;
    for (int it = 0; it < 8192; it++) {
        if (!(Ts < T_THRESH && !done)) break;
        float e_cur = region_ent(xd, ys, yd, tid);
        bool c1 = false, c2 = false, c3 = false;
        if (xd + 1 < HH)       c1 = region_ent(xd + 1, ys, yd, tid) > e_cur;
        if (!c1 && ys - 1 >= 0) c2 = region_ent(xd, ys - 1, yd, tid) > e_cur;
        if (!c1 && !c2 && yd + 1 < WW) {
            int ydn = yd + 1 < WW ? yd + 1 : WW;
            c3 = region_ent(xd, ys, ydn, tid) > e_cur;
        }
        if (c1) xd = xd + 1;
        if (c2) ys = ys - 1;
        if (c3) yd = yd + 1;
        done = !(c1 || c2 || c3);
        Ts = region_ent(xd, ys, yd, tid) / total;
    }
    if (tid == 0) {
        g_region[0] = 0; g_region[1] = xd;
        g_region[2] = ys; g_region[3] = yd;
    }
}

// ------------------------- k8: region mean-pool per (b,c) --------------------
__global__ void k_pool(const float* __restrict__ x) {   // 8192 blocks, 128 threads
    int xd = g_region[1], ys = g_region[2], yd = g_region[3];
    int wlen = yd - ys;
    int cnt = xd * wlen;
    const float* p = x + (size_t)blockIdx.x * PLANE;
    float s = 0.0f;
    for (int i = threadIdx.x; i < cnt; i += blockDim.x) {
        int hh = i / wlen;
        int ww = ys + (i - hh * wlen);
        s += p[hh * WW + ww];
    }
    s = blockReduceSum(s);
    if (threadIdx.x == 0) {
        float area = (float)(cnt > 0 ? cnt : 1);
        g_pooled[blockIdx.x] = s / area;
    }
}

// ------------------------- k9: tiny GEMM [8,1024]@[1024,30] ------------------
__global__ void k_gemm(const float* __restrict__ wfc, float* __restrict__ out) {
    __shared__ float sp[BC];   // 32KB
    for (int i = threadIdx.x; i < BC; i += blockDim.x) sp[i] = g_pooled[i];
    __syncthreads();
    int tid = threadIdx.x;
    if (tid < 240) {
        int b = tid / 30, n = tid % 30;
        const float* pb = sp + b * CHANNELS;
        float a0 = 0.f, a1 = 0.f, a2 = 0.f, a3 = 0.f;
        #pragma unroll 4
        for (int c = 0; c < CHANNELS; c += 4) {
            a0 += pb[c + 0] * wfc[(c + 0) * 30 + n];
            a1 += pb[c + 1] * wfc[(c + 1) * 30 + n];
            a2 += pb[c + 2] * wfc[(c + 2) * 30 + n];
            a3 += pb[c + 3] * wfc[(c + 3) * 30 + n];
        }
        out[b * 30 + n] = (a0 + a1) + (a2 + a3);
    }
}

// ------------------------- launch -------------------------------------------
extern "C" void kernel_launch(void* const* d_in, const int* in_sizes, int n_in,
                              void* d_out, int out_size) {
    const float* x   = (const float*)d_in[0];
    const float* wfc = (const float*)d_in[1];
    float* out = (float*)d_out;

    k_zero_small<<<1, 1024>>>();
    k_total_hist<<<1184, 256>>>((const float4*)x, NELEM / 4);
    k_col0_hist<<<32, 256>>>(x);
    k_eklm_light<<<1, 256>>>();
    // heavy path (statistically dead on this input; flag-gated)
    k_zero_cell<<<448, 256>>>();
    k_cell_hist<<<448, 256>>>(x);
    k_cumsum_h<<<56, 256>>>();
    k_cumsum_w<<<56, 256>>>();
    k_eklm_loop<<<1, 256>>>();
    // epilogue
    k_pool<<<BC, 128>>>(x);
    k_gemm<<<1, 256>>>(wfc, out);
}

// round 2
// speedup vs baseline: 1.5145x; 1.5145x over previous
#include <cuda_runtime.h>
#include <math.h>

#define HH 56
#define WW 56
#define NB 256
#define BATCH 8
#define CHANNELS 1024
#define PLANE (HH*WW)           // 3136
#define BC (BATCH*CHANNELS)     // 8192
#define NELEM (BC*PLANE)        // 25,690,112
#define T_THRESH 0.9f

#define HIST_BLOCKS 296
#define HIST_THREADS 512

// ------------------------- device scratch (no allocations) -------------------
__device__ unsigned int g_tpart[HIST_BLOCKS * NB];   // total-hist partials
__device__ float g_ent_y[WW];                        // per-column entropies
__device__ unsigned int g_cell[HH*WW*NB];            // heavy path scratch (12.8MB)
__device__ int   g_region[4];                        // xs, xd, ys, yd
__device__ int   g_flag;                             // 1 => heavy path needed
__device__ float g_total_ent;
__device__ int   g_ys0;
__device__ float g_pooled[BC];

// ------------------------- helpers ------------------------------------------
__device__ __forceinline__ float blockReduceSum(float v) {
    __shared__ float s_red[32];
    unsigned lane = threadIdx.x & 31u;
    unsigned wid  = threadIdx.x >> 5;
    #pragma unroll
    for (int o = 16; o; o >>= 1) v += __shfl_xor_sync(0xffffffffu, v, o);
    if (lane == 0) s_red[wid] = v;
    __syncthreads();
    unsigned nw = (blockDim.x + 31u) >> 5;
    if (wid == 0) {
        float t = (lane < nw) ? s_red[lane] : 0.0f;
        #pragma unroll
        for (int o = 16; o; o >>= 1) t += __shfl_xor_sync(0xffffffffu, t, o);
        if (lane == 0) s_red[0] = t;
    }
    __syncthreads();
    float r = s_red[0];
    __syncthreads();
    return r;
}

__device__ __forceinline__ int bin_of(float v) {
    int b = (int)floorf(v * 256.0f);
    return b > 255 ? 255 : b;
}

// ------------------------- k1: full-image 256-bin histogram (partials) -------
__global__ void k_total_hist(const float4* __restrict__ x4, int n4) {
    __shared__ unsigned int sh[16 * NB];   // one replica per warp (16KB)
    for (int i = threadIdx.x; i < 16 * NB; i += blockDim.x) sh[i] = 0u;
    __syncthreads();
    unsigned int* h = sh + (threadIdx.x >> 5) * NB;
    int stride = gridDim.x * blockDim.x;
    for (int i = blockIdx.x * blockDim.x + threadIdx.x; i < n4; i += stride) {
        float4 v = x4[i];
        if (v.x >= 0.0f && v.x <= 1.0f) atomicAdd(&h[bin_of(v.x)], 1u);
        if (v.y >= 0.0f && v.y <= 1.0f) atomicAdd(&h[bin_of(v.y)], 1u);
        if (v.z >= 0.0f && v.z <= 1.0f) atomicAdd(&h[bin_of(v.z)], 1u);
        if (v.w >= 0.0f && v.w <= 1.0f) atomicAdd(&h[bin_of(v.w)], 1u);
    }
    __syncthreads();
    if (threadIdx.x < NB) {
        unsigned int s = 0;
        #pragma unroll
        for (int r = 0; r < 16; r++) s += sh[r * NB + threadIdx.x];
        g_tpart[blockIdx.x * NB + threadIdx.x] = s;   // plain store, no atomics
    }
}

// ------------------------- k2: per-column (row 0) entropy --------------------
// 56 blocks (one per w), 256 threads
__global__ void k_colent(const float* __restrict__ x) {
    __shared__ unsigned int sh[8 * NB];   // per-warp replicas
    for (int i = threadIdx.x; i < 8 * NB; i += blockDim.x) sh[i] = 0u;
    __syncthreads();
    int w = blockIdx.x;
    unsigned int* h = sh + (threadIdx.x >> 5) * NB;
    for (int bc = threadIdx.x; bc < BC; bc += blockDim.x) {
        float v = x[(size_t)bc * PLANE + w];   // h == 0
        if (v >= 0.0f && v <= 1.0f) atomicAdd(&h[bin_of(v)], 1u);
    }
    __syncthreads();
    // merge replicas: thread tid owns bin tid
    int tid = threadIdx.x;
    unsigned int cu = 0;
    #pragma unroll
    for (int r = 0; r < 8; r++) cu += sh[r * NB + tid];
    float c = (float)cu;
    float s = blockReduceSum(c);
    float p = c / s;
    float ent = -blockReduceSum(p * log2f(p + 1e-9f));
    if (tid == 0) g_ent_y[w] = ent;
}

// ------------------------- k3: decide (total entropy + argmax) ---------------
__global__ void k_decide() {   // 1 block, 256 threads (tid == bin)
    int tid = threadIdx.x;
    // reduce total-hist partials
    unsigned int cu = 0;
    for (int i = 0; i < HIST_BLOCKS; i++) cu += g_tpart[i * NB + tid];
    float c = (float)cu;
    float s = blockReduceSum(c);
    float p = c / s;
    float tot = -blockReduceSum(p * log2f(p + 1e-9f));

    __shared__ float s_ent[WW];
    if (tid < WW) s_ent[tid] = g_ent_y[tid];
    __syncthreads();
    if (tid == 0) {
        float bestEnt = -1e30f; int bestw = 0;
        for (int w = 0; w < WW; w++)
            if (s_ent[w] > bestEnt) { bestEnt = s_ent[w]; bestw = w; }
        float Ts0 = bestEnt / tot;
        if (Ts0 < T_THRESH) {
            g_flag = 1;
            g_ys0 = bestw;
            g_total_ent = tot;
        } else {
            g_flag = 0;
            g_region[0] = 0; g_region[1] = 1;
            g_region[2] = bestw; g_region[3] = bestw + 1;
        }
    }
}

// ------------------------- heavy path (flag-gated; statistically dead) -------
__global__ void k_zero_cell() {
    if (!g_flag) return;
    int stride = gridDim.x * blockDim.x;
    for (int i = blockIdx.x * blockDim.x + threadIdx.x; i < HH*WW*NB; i += stride)
        g_cell[i] = 0u;
}

// grid: 56 h x 2 whalf x 4 bc-chunks = 448 blocks
__global__ void k_cell_hist(const float* __restrict__ x) {
    if (!g_flag) return;
    __shared__ unsigned int sh[28 * NB];   // 28KB
    for (int i = threadIdx.x; i < 28 * NB; i += blockDim.x) sh[i] = 0u;
    __syncthreads();
    int h     = blockIdx.x % 56;
    int whalf = (blockIdx.x / 56) & 1;
    int chunk = blockIdx.x / 112;
    int bc0 = chunk * 2048;
    const int TOT = 2048 * 28;
    for (int i = threadIdx.x; i < TOT; i += blockDim.x) {
        int bc   = bc0 + i / 28;
        int wloc = i % 28;
        float v = x[(size_t)bc * PLANE + h * WW + whalf * 28 + wloc];
        if (v >= 0.0f && v <= 1.0f)
            atomicAdd(&sh[wloc * NB + bin_of(v)], 1u);
    }
    __syncthreads();
    for (int i = threadIdx.x; i < 28 * NB; i += blockDim.x) {
        unsigned int s = sh[i];
        if (s) atomicAdd(&g_cell[((size_t)(h * WW + whalf * 28 + (i >> 8))) * NB + (i & 255)], s);
    }
}

__global__ void k_cumsum_h() {   // 56 blocks (w), 256 threads (bin)
    if (!g_flag) return;
    int w = blockIdx.x, tid = threadIdx.x;
    unsigned int run = 0;
    for (int h = 0; h < HH; h++) {
        size_t idx = ((size_t)(h * WW + w)) * NB + tid;
        run += g_cell[idx];
        g_cell[idx] = run;
    }
}

__global__ void k_cumsum_w() {   // 56 blocks (h), 256 threads (bin)
    if (!g_flag) return;
    int h = blockIdx.x, tid = threadIdx.x;
    unsigned int run = 0;
    for (int w = 0; w < WW; w++) {
        size_t idx = ((size_t)(h * WW + w)) * NB + tid;
        run += g_cell[idx];
        g_cell[idx] = run;
    }
}

__device__ __forceinline__ float integA(int i, int j, int tid) {
    if (i <= 0 || j <= 0) return 0.0f;
    return (float)g_cell[((size_t)((i - 1) * WW + (j - 1))) * NB + tid];
}

__device__ float region_ent(int xd, int ys, int yd, int tid) {
    float a = integA(xd, yd, tid) - integA(xd, ys, tid);
    float s = blockReduceSum(a);
    float p = a / s;
    return -blockReduceSum(p * log2f(p + 1e-9f));
}

__global__ void k_eklm_loop() {   // 1 block, 256 threads
    if (!g_flag) return;
    int tid = threadIdx.x;
    int xd = 1, ys = g_ys0, yd = g_ys0 + 1;
    float total = g_total_ent;
    float Ts = region_ent(xd, ys, yd, tid) / total;
    bool done = false;
    for (int it = 0; it < 8192; it++) {
        if (!(Ts < T_THRESH && !done)) break;
        float e_cur = region_ent(xd, ys, yd, tid);
        bool c1 = false, c2 = false, c3 = false;
        if (xd + 1 < HH)        c1 = region_ent(xd + 1, ys, yd, tid) > e_cur;
        if (!c1 && ys - 1 >= 0) c2 = region_ent(xd, ys - 1, yd, tid) > e_cur;
        if (!c1 && !c2 && yd + 1 < WW)
            c3 = region_ent(xd, ys, yd + 1, tid) > e_cur;
        if (c1) xd = xd + 1;
        if (c2) ys = ys - 1;
        if (c3) yd = yd + 1;
        done = !(c1 || c2 || c3);
        Ts = region_ent(xd, ys, yd, tid) / total;
    }
    if (tid == 0) {
        g_region[0] = 0; g_region[1] = xd;
        g_region[2] = ys; g_region[3] = yd;
    }
}

// ------------------------- k8: region mean-pool per (b,c) --------------------
__global__ void k_pool(const float* __restrict__ x) {   // 8192 blocks, 128 threads
    int xd = g_region[1], ys = g_region[2], yd = g_region[3];
    int wlen = yd - ys;
    int cnt = xd * wlen;
    const float* p = x + (size_t)blockIdx.x * PLANE;
    float s = 0.0f;
    for (int i = threadIdx.x; i < cnt; i += blockDim.x) {
        int hh = i / wlen;
        int ww = ys + (i - hh * wlen);
        s += p[hh * WW + ww];
    }
    s = blockReduceSum(s);
    if (threadIdx.x == 0) {
        float area = (float)(cnt > 0 ? cnt : 1);
        g_pooled[blockIdx.x] = s / area;
    }
}

// ------------------------- k9: tiny GEMM [8,1024]@[1024,30] ------------------
// 1 block, 960 threads: (b, n, kslice) = 8 x 30 x 4
__global__ void k_gemm(const float* __restrict__ wfc, float* __restrict__ out) {
    __shared__ float sp[BC];            // 32KB
    __shared__ float spart[960];
    for (int i = threadIdx.x; i < BC; i += blockDim.x) sp[i] = g_pooled[i];
    __syncthreads();
    int tid = threadIdx.x;
    if (tid < 960) {
        int b = tid / 120;
        int r = tid % 120;
        int n = r / 4;
        int ks = r % 4;
        const float* pb = sp + b * CHANNELS + ks * 256;
        const float* wp = wfc + (size_t)(ks * 256) * 30 + n;
        float a0 = 0.f, a1 = 0.f;
        #pragma unroll 8
        for (int k = 0; k < 256; k += 2) {
            a0 += pb[k + 0] * wp[(k + 0) * 30];
            a1 += pb[k + 1] * wp[(k + 1) * 30];
        }
        spart[tid] = a0 + a1;
    }
    __syncthreads();
    if (tid < 240) {
        int base = tid * 4;
        float v = spart[base] + spart[base + 1] + spart[base + 2] + spart[base + 3];
        int b = tid / 30, n = tid % 30;
        out[b * 30 + n] = v;
    }
}

// ------------------------- launch -------------------------------------------
extern "C" void kernel_launch(void* const* d_in, const int* in_sizes, int n_in,
                              void* d_out, int out_size) {
    const float* x   = (const float*)d_in[0];
    const float* wfc = (const float*)d_in[1];
    float* out = (float*)d_out;

    k_total_hist<<<HIST_BLOCKS, HIST_THREADS>>>((const float4*)x, NELEM / 4);
    k_colent<<<WW, 256>>>(x);
    k_decide<<<1, 256>>>();
    // heavy path (flag-gated, statistically dead on this input)
    k_zero_cell<<<448, 256>>>();
    k_cell_hist<<<448, 256>>>(x);
    k_cumsum_h<<<56, 256>>>();
    k_cumsum_w<<<56, 256>>>();
    k_eklm_loop<<<1, 256>>>();
    // epilogue
    k_pool<<<BC, 128>>>(x);
    k_gemm<<<1, 960>>>(wfc, out);
}

// round 3
// speedup vs baseline: 2.2826x; 1.5072x over previous
#include <cuda_runtime.h>
#include <math.h>

#define HH 56
#define WW 56
#define NB 256
#define BATCH 8
#define CHANNELS 1024
#define PLANE (HH*WW)           // 3136
#define BC (BATCH*CHANNELS)     // 8192
#define NELEM (BC*PLANE)        // 25,690,112
#define T_THRESH 0.9f

#define HIST_BLOCKS 296
#define HIST_THREADS 512

// ------------------------- device scratch (no allocations) -------------------
__device__ unsigned int g_tpart[HIST_BLOCKS * NB];   // total-hist partials
__device__ float g_ent_y[WW];                        // per-column entropies
__device__ unsigned int g_cell[HH*WW*NB];            // heavy path scratch (12.8MB)
__device__ int   g_region[4];                        // xs, xd, ys, yd
__device__ int   g_flag;                             // 1 => heavy path needed
__device__ float g_total_ent;
__device__ int   g_ys0;
__device__ float g_pooled[BC];

// ------------------------- helpers ------------------------------------------
__device__ __forceinline__ float blockReduceSum(float v) {
    __shared__ float s_red[32];
    unsigned lane = threadIdx.x & 31u;
    unsigned wid  = threadIdx.x >> 5;
    #pragma unroll
    for (int o = 16; o; o >>= 1) v += __shfl_xor_sync(0xffffffffu, v, o);
    if (lane == 0) s_red[wid] = v;
    __syncthreads();
    unsigned nw = (blockDim.x + 31u) >> 5;
    if (wid == 0) {
        float t = (lane < nw) ? s_red[lane] : 0.0f;
        #pragma unroll
        for (int o = 16; o; o >>= 1) t += __shfl_xor_sync(0xffffffffu, t, o);
        if (lane == 0) s_red[0] = t;
    }
    __syncthreads();
    float r = s_red[0];
    __syncthreads();
    return r;
}

__device__ __forceinline__ int bin_of(float v) {
    int b = (int)floorf(v * 256.0f);
    return b > 255 ? 255 : b;
}

// ------------------------- k1: full-image 256-bin histogram (partials) -------
__global__ void k_total_hist(const float4* __restrict__ x4, int n4) {
    __shared__ unsigned int sh[16 * NB];   // one replica per warp (16KB)
    for (int i = threadIdx.x; i < 16 * NB; i += blockDim.x) sh[i] = 0u;
    __syncthreads();
    unsigned int* h = sh + (threadIdx.x >> 5) * NB;
    int stride = gridDim.x * blockDim.x;
    for (int i = blockIdx.x * blockDim.x + threadIdx.x; i < n4; i += stride) {
        float4 v = x4[i];
        if (v.x >= 0.0f && v.x <= 1.0f) atomicAdd(&h[bin_of(v.x)], 1u);
        if (v.y >= 0.0f && v.y <= 1.0f) atomicAdd(&h[bin_of(v.y)], 1u);
        if (v.z >= 0.0f && v.z <= 1.0f) atomicAdd(&h[bin_of(v.z)], 1u);
        if (v.w >= 0.0f && v.w <= 1.0f) atomicAdd(&h[bin_of(v.w)], 1u);
    }
    __syncthreads();
    if (threadIdx.x < NB) {
        unsigned int s = 0;
        #pragma unroll
        for (int r = 0; r < 16; r++) s += sh[r * NB + threadIdx.x];
        g_tpart[blockIdx.x * NB + threadIdx.x] = s;   // plain store
    }
}

// ------------------------- k2: per-column (row 0) entropy --------------------
__global__ void k_colent(const float* __restrict__ x) {   // 56 blocks, 256 thr
    __shared__ unsigned int sh[8 * NB];   // per-warp replicas
    for (int i = threadIdx.x; i < 8 * NB; i += blockDim.x) sh[i] = 0u;
    __syncthreads();
    int w = blockIdx.x;
    unsigned int* h = sh + (threadIdx.x >> 5) * NB;
    for (int bc = threadIdx.x; bc < BC; bc += blockDim.x) {
        float v = x[(size_t)bc * PLANE + w];   // h == 0
        if (v >= 0.0f && v <= 1.0f) atomicAdd(&h[bin_of(v)], 1u);
    }
    __syncthreads();
    int tid = threadIdx.x;
    unsigned int cu = 0;
    #pragma unroll
    for (int r = 0; r < 8; r++) cu += sh[r * NB + tid];
    float c = (float)cu;
    float s = blockReduceSum(c);
    float p = c / s;
    float ent = -blockReduceSum(p * log2f(p + 1e-9f));
    if (tid == 0) g_ent_y[w] = ent;
}

// ------------------------- k3: decide (total entropy + argmax) ---------------
__global__ void k_decide() {   // 1 block, 256 threads (tid == bin)
    int tid = threadIdx.x;
    unsigned int cu = 0;
    #pragma unroll 8
    for (int i = 0; i < HIST_BLOCKS; i++) cu += g_tpart[i * NB + tid];
    float c = (float)cu;
    float s = blockReduceSum(c);
    float p = c / s;
    float tot = -blockReduceSum(p * log2f(p + 1e-9f));

    __shared__ float s_ent[WW];
    if (tid < WW) s_ent[tid] = g_ent_y[tid];
    __syncthreads();
    if (tid == 0) {
        float bestEnt = -1e30f; int bestw = 0;
        for (int w = 0; w < WW; w++)
            if (s_ent[w] > bestEnt) { bestEnt = s_ent[w]; bestw = w; }
        float Ts0 = bestEnt / tot;
        if (Ts0 < T_THRESH) {
            g_flag = 1;
            g_ys0 = bestw;
            g_total_ent = tot;
        } else {
            g_flag = 0;
            g_region[0] = 0; g_region[1] = 1;
            g_region[2] = bestw; g_region[3] = bestw + 1;
        }
    }
}

// ------------------------- heavy path (flag-gated; statistically dead) -------
// grid: 112 blocks = 56 h x 2 whalf. Each block OWNS its 28 output cells:
// plain stores, no pre-zero, no global atomics.
__global__ void k_cell_hist(const float* __restrict__ x) {
    if (!g_flag) return;
    __shared__ unsigned int sh[28 * NB];   // 28KB
    for (int i = threadIdx.x; i < 28 * NB; i += blockDim.x) sh[i] = 0u;
    __syncthreads();
    int h     = blockIdx.x >> 1;
    int whalf = blockIdx.x & 1;
    const int TOT = BC * 28;
    for (int i = threadIdx.x; i < TOT; i += blockDim.x) {
        int bc   = i / 28;
        int wloc = i % 28;
        float v = x[(size_t)bc * PLANE + h * WW + whalf * 28 + wloc];
        if (v >= 0.0f && v <= 1.0f)
            atomicAdd(&sh[wloc * NB + bin_of(v)], 1u);
    }
    __syncthreads();
    for (int i = threadIdx.x; i < 28 * NB; i += blockDim.x)
        g_cell[((size_t)(h * WW + whalf * 28 + (i >> 8))) * NB + (i & 255)] = sh[i];
}

// grid: 256 blocks (one per bin): fused 2D integral in shared memory
__global__ void k_integral() {
    if (!g_flag) return;
    __shared__ unsigned int s[HH * WW];   // 12.25KB
    int bin = blockIdx.x;
    int tid = threadIdx.x;
    for (int i = tid; i < HH * WW; i += blockDim.x)
        s[i] = g_cell[(size_t)i * NB + bin];
    __syncthreads();
    if (tid < WW) {                 // cumsum along h
        unsigned int run = 0;
        for (int h = 0; h < HH; h++) { run += s[h * WW + tid]; s[h * WW + tid] = run; }
    }
    __syncthreads();
    if (tid < HH) {                 // cumsum along w
        unsigned int run = 0;
        for (int w = 0; w < WW; w++) { run += s[tid * WW + w]; s[tid * WW + w] = run; }
    }
    __syncthreads();
    for (int i = tid; i < HH * WW; i += blockDim.x)
        g_cell[(size_t)i * NB + bin] = s[i];
}

__device__ __forceinline__ float integA(int i, int j, int tid) {
    if (i <= 0 || j <= 0) return 0.0f;
    return (float)g_cell[((size_t)((i - 1) * WW + (j - 1))) * NB + tid];
}

__device__ float region_ent(int xd, int ys, int yd, int tid) {
    float a = integA(xd, yd, tid) - integA(xd, ys, tid);
    float s = blockReduceSum(a);
    float p = a / s;
    return -blockReduceSum(p * log2f(p + 1e-9f));
}

__global__ void k_eklm_loop() {   // 1 block, 256 threads
    if (!g_flag) return;
    int tid = threadIdx.x;
    int xd = 1, ys = g_ys0, yd = g_ys0 + 1;
    float total = g_total_ent;
    float Ts = region_ent(xd, ys, yd, tid) / total;
    bool done = false;
    for (int it = 0; it < 8192; it++) {
        if (!(Ts < T_THRESH && !done)) break;
        float e_cur = region_ent(xd, ys, yd, tid);
        bool c1 = false, c2 = false, c3 = false;
        if (xd + 1 < HH)        c1 = region_ent(xd + 1, ys, yd, tid) > e_cur;
        if (!c1 && ys - 1 >= 0) c2 = region_ent(xd, ys - 1, yd, tid) > e_cur;
        if (!c1 && !c2 && yd + 1 < WW)
            c3 = region_ent(xd, ys, yd + 1, tid) > e_cur;
        if (c1) xd = xd + 1;
        if (c2) ys = ys - 1;
        if (c3) yd = yd + 1;
        done = !(c1 || c2 || c3);
        Ts = region_ent(xd, ys, yd, tid) / total;
    }
    if (tid == 0) {
        g_region[0] = 0; g_region[1] = xd;
        g_region[2] = ys; g_region[3] = yd;
    }
}

// ------------------------- k8: region mean-pool, warp per (b,c) --------------
__global__ void k_pool(const float* __restrict__ x) {   // 1024 blocks, 256 thr
    int xd = g_region[1], ys = g_region[2], yd = g_region[3];
    int wlen = yd - ys;
    int cnt = xd * wlen;
    int warp = threadIdx.x >> 5;
    int lane = threadIdx.x & 31;
    int bc = blockIdx.x * 8 + warp;
    const float* p = x + (size_t)bc * PLANE;
    float s = 0.0f;
    for (int i = lane; i < cnt; i += 32) {
        int hh = i / wlen;
        int ww = ys + (i - hh * wlen);
        s += p[hh * WW + ww];
    }
    #pragma unroll
    for (int o = 16; o; o >>= 1) s += __shfl_xor_sync(0xffffffffu, s, o);
    if (lane == 0) g_pooled[bc] = s / (float)(cnt > 0 ? cnt : 1);
}

// ------------------------- k9: tiny GEMM, block per output element -----------
__global__ void k_gemm(const float* __restrict__ wfc, float* __restrict__ out) {
    int b = blockIdx.x / 30;
    int n = blockIdx.x % 30;
    int tid = threadIdx.x;
    const float* pb = g_pooled + b * CHANNELS;
    float acc = 0.0f;
    #pragma unroll
    for (int k = 0; k < 4; k++) {
        int c = tid + k * 256;
        acc += pb[c] * wfc[c * 30 + n];
    }
    acc = blockReduceSum(acc);
    if (tid == 0) out[b * 30 + n] = acc;
}

// ------------------------- launch -------------------------------------------
extern "C" void kernel_launch(void* const* d_in, const int* in_sizes, int n_in,
                              void* d_out, int out_size) {
    const float* x   = (const float*)d_in[0];
    const float* wfc = (const float*)d_in[1];
    float* out = (float*)d_out;

    k_total_hist<<<HIST_BLOCKS, HIST_THREADS>>>((const float4*)x, NELEM / 4);
    k_colent<<<WW, 256>>>(x);
    k_decide<<<1, 256>>>();
    // heavy path (flag-gated, statistically dead on this input)
    k_cell_hist<<<112, 256>>>(x);
    k_integral<<<NB, 128>>>();
    k_eklm_loop<<<1, 256>>>();
    // epilogue
    k_pool<<<BC / 8, 256>>>(x);
    k_gemm<<<240, 256>>>(wfc, out);
}

// round 4
// speedup vs baseline: 3.0418x; 1.3326x over previous
#include <cuda_runtime.h>
#include <math.h>

#define HH 56
#define WW 56
#define NB 256
#define BATCH 8
#define CHANNELS 1024
#define PLANE (HH*WW)           // 3136
#define BC (BATCH*CHANNELS)     // 8192
#define NELEM (BC*PLANE)        // 25,690,112
#define N4 (NELEM/4)            // 6,422,528 float4
#define T_THRESH 0.9f

#define HIST_BLOCKS 1184
#define HIST_THREADS 256

// ------------------------- device scratch (no allocations) -------------------
__device__ unsigned int g_total[NB];          // zeroed by k_decide each replay
__device__ unsigned int g_col0[WW*NB];        // zeroed by k_decide each replay
__device__ unsigned int g_cell[HH*WW*NB];     // heavy path scratch (12.8MB)
__device__ unsigned int g_bar;                // heavy path grid barrier
__device__ int   g_region[4];                 // xs, xd, ys, yd
__device__ int   g_flag;                      // 1 => heavy path needed
__device__ float g_total_ent;
__device__ int   g_ys0;
__device__ float g_pooled[BC];

// ------------------------- helpers ------------------------------------------
__device__ __forceinline__ float blockReduceSum(float v) {
    __shared__ float s_red[32];
    unsigned lane = threadIdx.x & 31u;
    unsigned wid  = threadIdx.x >> 5;
    #pragma unroll
    for (int o = 16; o; o >>= 1) v += __shfl_xor_sync(0xffffffffu, v, o);
    if (lane == 0) s_red[wid] = v;
    __syncthreads();
    unsigned nw = (blockDim.x + 31u) >> 5;
    if (wid == 0) {
        float t = (lane < nw) ? s_red[lane] : 0.0f;
        #pragma unroll
        for (int o = 16; o; o >>= 1) t += __shfl_xor_sync(0xffffffffu, t, o);
        if (lane == 0) s_red[0] = t;
    }
    __syncthreads();
    float r = s_red[0];
    __syncthreads();
    return r;
}

__device__ __forceinline__ float warpReduceSum(float v) {
    #pragma unroll
    for (int o = 16; o; o >>= 1) v += __shfl_xor_sync(0xffffffffu, v, o);
    return v;
}

__device__ __forceinline__ int bin_of(float v) {   // caller guarantees v >= 0
    int b = (int)(v * 256.0f);
    return b > 255 ? 255 : b;
}

// ------------------------- k1: fused total + column-0 histograms -------------
__global__ void k_hist(const float4* __restrict__ x4) {
    __shared__ unsigned int sh[8 * NB];   // per-warp replicas, 8KB
    for (int i = threadIdx.x; i < 8 * NB; i += blockDim.x) sh[i] = 0u;
    __syncthreads();
    unsigned int* h = sh + (threadIdx.x >> 5) * NB;
    int stride = gridDim.x * blockDim.x;
    for (int i = blockIdx.x * blockDim.x + threadIdx.x; i < N4; i += stride) {
        float4 v = x4[i];
        int b0 = bin_of(v.x), b1 = bin_of(v.y), b2 = bin_of(v.z), b3 = bin_of(v.w);
        bool v0 = (v.x >= 0.0f && v.x <= 1.0f);
        bool v1 = (v.y >= 0.0f && v.y <= 1.0f);
        bool v2 = (v.z >= 0.0f && v.z <= 1.0f);
        bool v3 = (v.w >= 0.0f && v.w <= 1.0f);
        if (v0) atomicAdd(&h[b0], 1u);
        if (v1) atomicAdd(&h[b1], 1u);
        if (v2) atomicAdd(&h[b2], 1u);
        if (v3) atomicAdd(&h[b3], 1u);
        // column-0 (h==0) side histogram: element base 4i; h==0 iff (i % 784) < 14
        int m = i % 784;
        if (m < 14) {
            int w = 4 * m;
            if (v0) atomicAdd(&g_col0[(w + 0) * NB + b0], 1u);
            if (v1) atomicAdd(&g_col0[(w + 1) * NB + b1], 1u);
            if (v2) atomicAdd(&g_col0[(w + 2) * NB + b2], 1u);
            if (v3) atomicAdd(&g_col0[(w + 3) * NB + b3], 1u);
        }
    }
    __syncthreads();
    // merge warp replicas into global (g_total zeroed by k_decide of prior replay)
    int tid = threadIdx.x;   // blockDim == NB
    unsigned int s = 0;
    #pragma unroll
    for (int r = 0; r < 8; r++) s += sh[r * NB + tid];
    if (s) atomicAdd(&g_total[tid], s);
}

// ------------------------- k2: decide (entropies + argmax + flag) ------------
__global__ void k_decide() {   // 1 block, 256 threads
    int tid = threadIdx.x;
    int lane = tid & 31, wrp = tid >> 5;

    // total entropy (tid == bin)
    float c = (float)g_total[tid];
    float s = blockReduceSum(c);
    float p = c / s;
    float tot = -blockReduceSum(p * log2f(p + 1e-9f));

    // per-column entropies: warp per column
    __shared__ float s_ent[WW];
    for (int w = wrp; w < WW; w += 8) {
        float cs = 0.0f;
        float cc[8];
        #pragma unroll
        for (int k = 0; k < 8; k++) {
            cc[k] = (float)g_col0[w * NB + lane + k * 32];
            cs += cc[k];
        }
        cs = warpReduceSum(cs);
        float e = 0.0f;
        #pragma unroll
        for (int k = 0; k < 8; k++) {
            float pp = cc[k] / cs;
            e += pp * log2f(pp + 1e-9f);
        }
        e = -warpReduceSum(e);
        if (lane == 0) s_ent[w] = e;
    }
    __syncthreads();
    if (tid == 0) {
        float bestEnt = -1e30f; int bestw = 0;
        for (int w = 0; w < WW; w++)
            if (s_ent[w] > bestEnt) { bestEnt = s_ent[w]; bestw = w; }
        float Ts0 = bestEnt / tot;
        if (Ts0 < T_THRESH) {
            g_flag = 1;
            g_ys0 = bestw;
            g_total_ent = tot;
        } else {
            g_flag = 0;
            g_region[0] = 0; g_region[1] = 1;
            g_region[2] = bestw; g_region[3] = bestw + 1;
        }
    }
    __syncthreads();
    // re-zero accumulators for the next graph replay
    g_total[tid] = 0u;
    for (int j = tid; j < WW * NB; j += 256) g_col0[j] = 0u;
}

// ------------------------- k3: heavy path, ONE kernel (flag-gated) -----------
__device__ __forceinline__ float integA(int i, int j, int tid) {
    if (i <= 0 || j <= 0) return 0.0f;
    return (float)g_cell[((size_t)((i - 1) * WW + (j - 1))) * NB + tid];
}

__device__ float region_ent(int xd, int ys, int yd, int tid) {
    float a = integA(xd, yd, tid) - integA(xd, ys, tid);
    float s = blockReduceSum(a);
    float p = a / s;
    return -blockReduceSum(p * log2f(p + 1e-9f));
}

// 112 blocks (single wave, all resident), 256 threads, 28KB smem
__global__ void __launch_bounds__(256) k_heavy(const float* __restrict__ x) {
    if (!g_flag) return;
    __shared__ unsigned int sh[28 * NB];   // 28KB; phase2 reuses first 12.5KB
    int tid = threadIdx.x;

    // ---- phase 1: per-(h,w)-cell histograms (block owns 28 cells) ----
    for (int i = tid; i < 28 * NB; i += blockDim.x) sh[i] = 0u;
    __syncthreads();
    int h     = blockIdx.x >> 1;
    int whalf = blockIdx.x & 1;
    const int TOT = BC * 28;
    for (int i = tid; i < TOT; i += blockDim.x) {
        int bc   = i / 28;
        int wloc = i % 28;
        float v = x[(size_t)bc * PLANE + h * WW + whalf * 28 + wloc];
        if (v >= 0.0f && v <= 1.0f)
            atomicAdd(&sh[wloc * NB + bin_of(v)], 1u);
    }
    __syncthreads();
    for (int i = tid; i < 28 * NB; i += blockDim.x)
        g_cell[((size_t)(h * WW + whalf * 28 + (i >> 8))) * NB + (i & 255)] = sh[i];

    // ---- grid barrier 1 (all 112 blocks resident: single wave) ----
    __threadfence();
    __syncthreads();
    if (tid == 0) atomicAdd(&g_bar, 1u);
    if (tid == 0) { while (atomicAdd(&g_bar, 0u) < 112u) { } }
    __syncthreads();
    __threadfence();

    // ---- phase 2: 2D integral per bin ----
    unsigned int* s = sh;   // reuse: HH*WW = 3136 words
    for (int bin = blockIdx.x; bin < NB; bin += gridDim.x) {
        for (int i = tid; i < HH * WW; i += blockDim.x)
            s[i] = g_cell[(size_t)i * NB + bin];
        __syncthreads();
        if (tid < WW) {
            unsigned int run = 0;
            for (int hh = 0; hh < HH; hh++) { run += s[hh * WW + tid]; s[hh * WW + tid] = run; }
        }
        __syncthreads();
        if (tid < HH) {
            unsigned int run = 0;
            for (int w = 0; w < WW; w++) { run += s[tid * WW + w]; s[tid * WW + w] = run; }
        }
        __syncthreads();
        for (int i = tid; i < HH * WW; i += blockDim.x)
            g_cell[(size_t)i * NB + bin] = s[i];
        __syncthreads();
    }

    // ---- grid barrier 2: only block 0 waits; others arrive & exit ----
    __threadfence();
    __syncthreads();
    if (tid == 0) atomicAdd(&g_bar, 1u);
    if (blockIdx.x != 0) return;
    if (tid == 0) { while (atomicAdd(&g_bar, 0u) < 224u) { } }
    __syncthreads();
    __threadfence();

    // ---- phase 3: greedy EKLM loop (block 0, 256 threads) ----
    int xd = 1, ys = g_ys0, yd = g_ys0 + 1;
    float total = g_total_ent;
    float Ts = region_ent(xd, ys, yd, tid) / total;
    bool done = false;
    for (int it = 0; it < 8192; it++) {
        if (!(Ts < T_THRESH && !done)) break;
        float e_cur = region_ent(xd, ys, yd, tid);
        bool c1 = false, c2 = false, c3 = false;
        if (xd + 1 < HH)        c1 = region_ent(xd + 1, ys, yd, tid) > e_cur;
        if (!c1 && ys - 1 >= 0) c2 = region_ent(xd, ys - 1, yd, tid) > e_cur;
        if (!c1 && !c2 && yd + 1 < WW)
            c3 = region_ent(xd, ys, yd + 1, tid) > e_cur;
        if (c1) xd = xd + 1;
        if (c2) ys = ys - 1;
        if (c3) yd = yd + 1;
        done = !(c1 || c2 || c3);
        Ts = region_ent(xd, ys, yd, tid) / total;
    }
    if (tid == 0) {
        g_region[0] = 0; g_region[1] = xd;
        g_region[2] = ys; g_region[3] = yd;
        g_bar = 0u;   // reset barrier for next replay
    }
}

// ------------------------- k4: region mean-pool, warp per (b,c) --------------
__global__ void k_pool(const float* __restrict__ x) {   // 1024 blocks, 256 thr
    int xd = g_region[1], ys = g_region[2], yd = g_region[3];
    int wlen = yd - ys;
    int cnt = xd * wlen;
    int warp = threadIdx.x >> 5;
    int lane = threadIdx.x & 31;
    int bc = blockIdx.x * 8 + warp;
    const float* p = x + (size_t)bc * PLANE;
    float s = 0.0f;
    for (int i = lane; i < cnt; i += 32) {
        int hh = i / wlen;
        int ww = ys + (i - hh * wlen);
        s += p[hh * WW + ww];
    }
    #pragma unroll
    for (int o = 16; o; o >>= 1) s += __shfl_xor_sync(0xffffffffu, s, o);
    if (lane == 0) g_pooled[bc] = s / (float)(cnt > 0 ? cnt : 1);
}

// ------------------------- k5: tiny GEMM, block per output element -----------
__global__ void k_gemm(const float* __restrict__ wfc, float* __restrict__ out) {
    int b = blockIdx.x / 30;
    int n = blockIdx.x % 30;
    int tid = threadIdx.x;
    const float* pb = g_pooled + b * CHANNELS;
    float acc = 0.0f;
    #pragma unroll
    for (int k = 0; k < 4; k++) {
        int c = tid + k * 256;
        acc += pb[c] * wfc[c * 30 + n];
    }
    acc = blockReduceSum(acc);
    if (tid == 0) out[b * 30 + n] = acc;
}

// ------------------------- launch -------------------------------------------
extern "C" void kernel_launch(void* const* d_in, const int* in_sizes, int n_in,
                              void* d_out, int out_size) {
    const float* x   = (const float*)d_in[0];
    const float* wfc = (const float*)d_in[1];
    float* out = (float*)d_out;

    k_hist<<<HIST_BLOCKS, HIST_THREADS>>>((const float4*)x);
    k_decide<<<1, 256>>>();
    k_heavy<<<112, 256>>>(x);      // flag-gated, statistically dead
    k_pool<<<BC / 8, 256>>>(x);
    k_gemm<<<240, 256>>>(wfc, out);
}